// round 12
// baseline (speedup 1.0000x reference)
#include <cuda_runtime.h>
#include <math.h>
#include <stdint.h>

#define B_  32
#define S1_ 128
#define T_  50
#define E_  768
#define H_  1024
#define V_  32000

// ---------------- device scratch (no allocation allowed) ----------------
__device__ float g_xW[B_ * S1_ * H_];      // x @ W1x^T (precomputed once)
__device__ float g_scores[B_ * S1_];       // scores -> logw
__device__ float g_inp0[B_ * 2 * E_];      // [emb_t ; context]
__device__ float g_h[3 * B_ * H_];
__device__ float g_c[3 * B_ * H_];
__device__ float g_bsum[3 * 4 * H_];       // bih + bhh per layer
__device__ float g_part[32 * B_ * 4 * H_]; // split-K partials
__device__ float g_fcpart[2 * B_ * V_];    // fc split-K partials (2 x 32 x 32000)

// ---------------- f32x2 packed helpers ----------------
__device__ __forceinline__ unsigned long long ffma2_(unsigned long long a,
                                                     unsigned long long b,
                                                     unsigned long long c) {
    unsigned long long d;
    asm("fma.rn.f32x2 %0, %1, %2, %3;" : "=l"(d) : "l"(a), "l"(b), "l"(c));
    return d;
}
__device__ __forceinline__ unsigned long long bcast2_(float x) {
    unsigned long long r;
    asm("mov.b64 %0, {%1, %1};" : "=l"(r) : "f"(x));
    return r;
}
__device__ __forceinline__ void unpack2_(unsigned long long v, float& lo, float& hi) {
    asm("mov.b64 {%0, %1}, %2;" : "=f"(lo), "=f"(hi) : "l"(v));
}
// TF32 operand rounding (matches cublas TF32 path: cvt.rna)
__device__ __forceinline__ float tf32r(float x) {
    unsigned u;
    asm("cvt.rna.tf32.f32 %0, %1;" : "=r"(u) : "f"(x));
    return __uint_as_float(u);
}

#define SHA_STRIDE 1152   // 32*36
#define SHW_STRIDE 2112   // 32*66

// ---------------- shared GEMM core: 32 rows x 64 cols per block, 128 threads
// Ping-pong double-buffered smem: ONE __syncthreads per K-chunk.
__device__ __forceinline__ void gemm_core32(
    const float* __restrict__ A, int ldA,
    const float* __restrict__ W, int ldW,
    int kbase, int NC, int nbase,
    float* __restrict__ dst, int Nout,
    float* shA, float* shW)
{
    const int tid = threadIdx.x;
    const int ng  = tid & 31;
    const int mg  = tid >> 5;
    const int m0  = mg * 8;

    unsigned long long acc0[4], acc1[4];
#pragma unroll
    for (int r = 0; r < 4; r++) { acc0[r] = 0ull; acc1[r] = 0ull; }

    float4 aR[2], wR[4];
    auto loadChunk = [&](int c) {
        const int k0 = kbase + c * 32;
#pragma unroll
        for (int j = 0; j < 2; j++) {
            const int f4 = tid + j * 128;
            const int m  = f4 >> 3, kq = f4 & 7;
            aR[j] = *reinterpret_cast<const float4*>(&A[(size_t)m * ldA + k0 + kq * 4]);
        }
#pragma unroll
        for (int j = 0; j < 4; j++) {
            const int f4 = tid + j * 128;
            const int r  = f4 >> 3, kq = f4 & 7;
            wR[j] = *reinterpret_cast<const float4*>(
                &W[(size_t)(nbase + r) * ldW + k0 + kq * 4]);
        }
    };

    loadChunk(0);
    for (int c = 0; c < NC; c++) {
        float* sA = shA + (c & 1) * SHA_STRIDE;
        float* sW = shW + (c & 1) * SHW_STRIDE;
        // store staged regs to this chunk's buffer (with TF32 rounding)
#pragma unroll
        for (int j = 0; j < 2; j++) {
            const int f4 = tid + j * 128;
            const int m  = f4 >> 3, kq = f4 & 7;
            sA[(kq * 4 + 0) * 36 + m] = tf32r(aR[j].x);
            sA[(kq * 4 + 1) * 36 + m] = tf32r(aR[j].y);
            sA[(kq * 4 + 2) * 36 + m] = tf32r(aR[j].z);
            sA[(kq * 4 + 3) * 36 + m] = tf32r(aR[j].w);
        }
#pragma unroll
        for (int j = 0; j < 4; j++) {
            const int f4 = tid + j * 128;
            const int r  = f4 >> 3, kq = f4 & 7;
            sW[(kq * 4 + 0) * 66 + r] = tf32r(wR[j].x);
            sW[(kq * 4 + 1) * 66 + r] = tf32r(wR[j].y);
            sW[(kq * 4 + 2) * 66 + r] = tf32r(wR[j].z);
            sW[(kq * 4 + 3) * 66 + r] = tf32r(wR[j].w);
        }
        __syncthreads();
        if (c + 1 < NC) loadChunk(c + 1);   // prefetch next chunk into regs

#pragma unroll
        for (int kk = 0; kk < 32; kk++) {
            const ulonglong2 a01 = *reinterpret_cast<const ulonglong2*>(&sA[kk * 36 + m0]);
            const ulonglong2 a23 = *reinterpret_cast<const ulonglong2*>(&sA[kk * 36 + m0 + 4]);
            const float2 wv = *reinterpret_cast<const float2*>(&sW[kk * 66 + 2 * ng]);
            const unsigned long long w0 = bcast2_(wv.x);
            const unsigned long long w1 = bcast2_(wv.y);
            acc0[0] = ffma2_(a01.x, w0, acc0[0]);
            acc0[1] = ffma2_(a01.y, w0, acc0[1]);
            acc0[2] = ffma2_(a23.x, w0, acc0[2]);
            acc0[3] = ffma2_(a23.y, w0, acc0[3]);
            acc1[0] = ffma2_(a01.x, w1, acc1[0]);
            acc1[1] = ffma2_(a01.y, w1, acc1[1]);
            acc1[2] = ffma2_(a23.x, w1, acc1[2]);
            acc1[3] = ffma2_(a23.y, w1, acc1[3]);
        }
        // no second sync: next iteration's STS targets the other buffer, and
        // every warp past the barrier above has finished compute of chunk c-1.
    }

    const int n0 = nbase + 2 * ng;
#pragma unroll
    for (int r = 0; r < 4; r++) {
        float lo, hi;
        const int m = m0 + 2 * r;
        unpack2_(acc0[r], lo, hi);
        dst[(size_t)m * Nout + n0]           = lo;
        dst[(size_t)(m + 1) * Nout + n0]     = hi;
        unpack2_(acc1[r], lo, hi);
        dst[(size_t)m * Nout + n0 + 1]       = lo;
        dst[(size_t)(m + 1) * Nout + n0 + 1] = hi;
    }
}

// ---------------- carrier: main split-K GEMM (two segments over blockIdx.y)
// plus piggybacked fc partial tiles (blockIdx.x >= mainBx).
// fc: 1000 tiles total = 2 K-slices (K=512, 16 chunks) x 500 n-tiles.
__global__ void __launch_bounds__(128) carrier(
    const float* __restrict__ Ain, int ldAa, const float* __restrict__ WA, int ldWA,
    int KsA, int yA,
    const float* __restrict__ Bin, int ldBb, const float* __restrict__ WB, int ldWB,
    int KsB,
    int mainBx, int N,
    const float* __restrict__ fcA, const float* __restrict__ fcW,
    int fcBase, int fcCount)
{
    __shared__ __align__(16) float shA[2 * SHA_STRIDE];
    __shared__ __align__(16) float shW[2 * SHW_STRIDE];
    const int bx = blockIdx.x, by = blockIdx.y;

    if (bx < mainBx) {
        const float* A; int ldA; const float* W; int ldW; int Ks, kb;
        if (by < yA) { A = Ain; ldA = ldAa; W = WA; ldW = ldWA; Ks = KsA; kb = by * KsA; }
        else         { A = Bin; ldA = ldBb; W = WB; ldW = ldWB; Ks = KsB; kb = (by - yA) * KsB; }
        gemm_core32(A, ldA, W, ldW, kb, Ks >> 5, bx * 64,
                    g_part + (size_t)by * 32 * N, N, shA, shW);
    } else {
        const int local = (bx - mainBx) * gridDim.y + by;
        if (local >= fcCount) return;
        const int flat  = fcBase + local;
        const int slice = flat / 500;
        const int tile  = flat - slice * 500;
        gemm_core32(fcA, H_, fcW, H_, slice * 512, 16, tile * 64,
                    g_fcpart + (size_t)slice * B_ * V_, V_, shA, shW);
    }
}

// ---------------- xW precompute: g_xW = x @ W1x^T (4096 rows via blockIdx.z)
__global__ void __launch_bounds__(128) gemm_xw(const float* __restrict__ x,
                                               const float* __restrict__ W1)
{
    __shared__ __align__(16) float shA[2 * SHA_STRIDE];
    __shared__ __align__(16) float shW[2 * SHW_STRIDE];
    const int z = blockIdx.z;
    gemm_core32(x + (size_t)z * 32 * E_, E_, W1, E_ + H_, 0, E_ / 32, blockIdx.x * 64,
                g_xW + (size_t)z * 32 * H_, H_, shA, shW);
}

// ---------------- attn part 1: hW reduce(+b1, 32 slices) -> scores -> logw ----
__global__ void __launch_bounds__(1024) attn_sc(
    const float* __restrict__ w2, const float* __restrict__ b2p,
    const float* __restrict__ b1)
{
    const int b = blockIdx.x, tid = threadIdx.x;
    __shared__ float hw[H_];
    __shared__ float w2s[H_];
    __shared__ float sc[S1_];
    __shared__ float red4[4];

    {   // hW = b1 + sum of 32 partials (N=1024 layout in g_part)
        float v = b1[tid];
#pragma unroll
        for (int ks = 0; ks < 32; ks++)
            v += g_part[(size_t)(ks * 32 + b) * H_ + tid];
        hw[tid]  = v;
        w2s[tid] = w2[tid];
    }
    __syncthreads();

    const int lane = tid & 31, w = tid >> 5;
#pragma unroll
    for (int r = 0; r < 4; r++) {
        const int s = r * 32 + w;
        const float* xw = g_xW + ((size_t)b * S1_ + s) * H_;
        float p = 0.f;
#pragma unroll 8
        for (int i = 0; i < 32; i++) {
            const int hh = i * 32 + lane;
            float v = xw[hh] + hw[hh];
            v = fmaxf(v, 0.f);
            p += v * w2s[hh];
        }
#pragma unroll
        for (int o = 16; o > 0; o >>= 1) p += __shfl_xor_sync(0xffffffffu, p, o);
        if (lane == 0) sc[s] = p + b2p[0];
    }
    __syncthreads();

    if (tid < 128) {
        float v = sc[tid];
#pragma unroll
        for (int o = 16; o > 0; o >>= 1) v = fmaxf(v, __shfl_xor_sync(0xffffffffu, v, o));
        if (lane == 0) red4[w] = v;
    }
    __syncthreads();
    const float mx = fmaxf(fmaxf(red4[0], red4[1]), fmaxf(red4[2], red4[3]));
    __syncthreads();
    if (tid < 128) {
        const float sh = sc[tid] - mx;
        sc[tid] = sh;
        float e = expf(sh);
#pragma unroll
        for (int o = 16; o > 0; o >>= 1) e += __shfl_xor_sync(0xffffffffu, e, o);
        if (lane == 0) red4[w] = e;
    }
    __syncthreads();
    if (tid < 128) {
        const float lse = logf(red4[0] + red4[1] + red4[2] + red4[3]);
        g_scores[b * S1_ + tid] = sc[tid] - lse;   // logw
    }
}

// ---------------- attn part 2: context + emb gather -> inp0 ----------------
__global__ void __launch_bounds__(512) attn_ctx(const float* __restrict__ x,
                                                const int* __restrict__ tseq,
                                                const float* __restrict__ emb,
                                                int t)
{
    const int c = blockIdx.x, b = blockIdx.y, tid = threadIdx.x;
    const int et = tid & 127, sq = tid >> 7;
    __shared__ float sc[128];
    __shared__ float acc[4 * 128];

    if (tid < 128) sc[tid] = g_scores[b * S1_ + tid];
    __syncthreads();

    const int e = c * 128 + et;           // e in [0,768)
    const float* xb = x + ((size_t)b * S1_ + sq * 32) * E_ + e;
    float ctx = 0.f;
#pragma unroll 8
    for (int s = 0; s < 32; s++) ctx += sc[sq * 32 + s] * xb[(size_t)s * E_];
    acc[sq * 128 + et] = ctx;
    __syncthreads();
    if (tid < 128) {
        const float v = acc[tid] + acc[128 + tid] + acc[256 + tid] + acc[384 + tid];
        const int ee = c * 128 + tid;
        g_inp0[b * 2 * E_ + E_ + ee] = v;
        const int tgt = tseq[b * T_ + t];
        g_inp0[b * 2 * E_ + ee] = emb[(size_t)tgt * E_ + ee];
    }
}

// ---------------- LSTM pointwise update (16 partials + biases) ----------------
__device__ __forceinline__ void lstm_update(int l, int b)
{
    const int j = threadIdx.x;
    float gi = g_bsum[l * 4 * H_ + j];
    float gf = g_bsum[l * 4 * H_ + H_ + j];
    float gg = g_bsum[l * 4 * H_ + 2 * H_ + j];
    float go = g_bsum[l * 4 * H_ + 3 * H_ + j];
#pragma unroll
    for (int ks = 0; ks < 16; ks++) {
        const float* p = g_part + (size_t)(ks * 32 + b) * 4 * H_;
        gi += p[j];
        gf += p[H_ + j];
        gg += p[2 * H_ + j];
        go += p[3 * H_ + j];
    }
    float* cp = g_c + (size_t)(l * B_ + b) * H_ + j;
    float* hp = g_h + (size_t)(l * B_ + b) * H_ + j;
    const float si = 1.f / (1.f + expf(-gi));
    const float sf = 1.f / (1.f + expf(-gf));
    const float so = 1.f / (1.f + expf(-go));
    const float cn = sf * (*cp) + si * tanhf(gg);
    *cp = cn;
    *hp = so * tanhf(cn);
}

__global__ void __launch_bounds__(1024) lstm_pw(int l) { lstm_update(l, blockIdx.x); }

// ---------------- logits from 2 fc partials + log_softmax (one batch row) ----
__device__ __forceinline__ void logsoftmax_row(float* __restrict__ rowBase,
                                               const float* __restrict__ fcb, int b)
{
    float* row = rowBase + (size_t)b * ((long long)T_ * V_);
    const int tid = threadIdx.x;
    const int NV4 = V_ / 4;
    const float4* bb = (const float4*)fcb;
    const float4* p0 = (const float4*)(g_fcpart + (size_t)b * V_);
    const float4* p1 = (const float4*)(g_fcpart + (size_t)(B_ + b) * V_);
    float4* r4 = (float4*)row;
    __shared__ float red[1024];

    float m = -1e30f;
    for (int v = tid; v < NV4; v += 1024) {
        const float4 a = bb[v], q0 = p0[v], q1 = p1[v];
        float4 r;
        r.x = a.x + q0.x + q1.x;
        r.y = a.y + q0.y + q1.y;
        r.z = a.z + q0.z + q1.z;
        r.w = a.w + q0.w + q1.w;
        r4[v] = r;
        m = fmaxf(m, fmaxf(fmaxf(r.x, r.y), fmaxf(r.z, r.w)));
    }
    red[tid] = m; __syncthreads();
    for (int st = 512; st > 0; st >>= 1) {
        if (tid < st) red[tid] = fmaxf(red[tid], red[tid + st]);
        __syncthreads();
    }
    m = red[0];
    __syncthreads();

    float s = 0.f;
    for (int v = tid; v < NV4; v += 1024) {
        const float4 r = r4[v];
        s += expf(r.x - m) + expf(r.y - m) + expf(r.z - m) + expf(r.w - m);
    }
    red[tid] = s; __syncthreads();
    for (int st = 512; st > 0; st >>= 1) {
        if (tid < st) red[tid] += red[tid + st];
        __syncthreads();
    }
    const float lse = logf(red[0]);

    for (int v = tid; v < NV4; v += 1024) {
        float4 r = r4[v];
        r.x = (r.x - m) - lse;
        r.y = (r.y - m) - lse;
        r.z = (r.z - m) - lse;
        r.w = (r.w - m) - lse;
        r4[v] = r;
    }
}

// blocks 0..31: lp2(t); blocks 32..63: log_softmax for step t-1 (if any)
__global__ void __launch_bounds__(1024) lp2_ls(float* outPrevBase, const float* __restrict__ fcb)
{
    if (blockIdx.x < 32) {
        lstm_update(2, blockIdx.x);
    } else {
        if (!outPrevBase) return;
        logsoftmax_row(outPrevBase, fcb, blockIdx.x - 32);
    }
}

__global__ void __launch_bounds__(1024) ls_final(float* outBase, const float* __restrict__ fcb)
{
    logsoftmax_row(outBase, fcb, blockIdx.x);
}

// ---------------- init kernels ----------------
__global__ void zero_state()
{
    const int idx = blockIdx.x * 1024 + threadIdx.x;
    if (idx < 3 * B_ * H_) { g_h[idx] = 0.f; g_c[idx] = 0.f; }
}
__global__ void bias_sum(const float* bi0, const float* bh0,
                         const float* bi1, const float* bh1,
                         const float* bi2, const float* bh2)
{
    const int i = blockIdx.x * 1024 + threadIdx.x;
    if (i < 4 * H_) {
        g_bsum[i]          = bi0[i] + bh0[i];
        g_bsum[4 * H_ + i] = bi1[i] + bh1[i];
        g_bsum[8 * H_ + i] = bi2[i] + bh2[i];
    }
}

// ---------------- launch ----------------
extern "C" void kernel_launch(void* const* d_in, const int* in_sizes, int n_in,
                              void* d_out, int out_size)
{
    const float* x    = (const float*)d_in[0];
    const int*   tseq = (const int*)  d_in[1];
    const float* emb  = (const float*)d_in[2];
    const float* W1   = (const float*)d_in[3];   // (H, E+H)
    const float* b1   = (const float*)d_in[4];
    const float* W2   = (const float*)d_in[5];   // (1, H)
    const float* b2   = (const float*)d_in[6];

    const float *fcW, *fcb;
    const float *Wih[3], *Whh[3], *bih[3], *bhh[3];
    int base;
    if (in_sizes[7] == V_ * H_) {          // dict order (expected)
        fcW = (const float*)d_in[7];
        fcb = (const float*)d_in[8];
        base = 9;
    } else {                                // signature order (fallback)
        fcW = (const float*)d_in[19];
        fcb = (const float*)d_in[20];
        base = 7;
    }
    for (int l = 0; l < 3; l++) {
        Wih[l] = (const float*)d_in[base + 4 * l + 0];
        Whh[l] = (const float*)d_in[base + 4 * l + 1];
        bih[l] = (const float*)d_in[base + 4 * l + 2];
        bhh[l] = (const float*)d_in[base + 4 * l + 3];
    }
    float* out = (float*)d_out;

    float *inp0, *h;
    cudaGetSymbolAddress((void**)&inp0, g_inp0);
    cudaGetSymbolAddress((void**)&h,    g_h);
    float* h0 = h;
    float* h1 = h + B_ * H_;
    float* h2 = h + 2 * B_ * H_;

    zero_state<<<96, 1024>>>();
    bias_sum<<<4, 1024>>>(bih[0], bhh[0], bih[1], bhh[1], bih[2], bhh[2]);
    gemm_xw<<<dim3(16, 1, (B_ * S1_) / 32), 128>>>(x, W1);

    for (int t = 0; t < T_; t++) {
        const bool hasFc = (t > 0);
        const int  cnt   = hasFc ? 250 : 0;        // fc tiles per carrier
        const int  exHW  = hasFc ? 8  : 0;         // ceil(250/32)
        const int  exG   = hasFc ? 16 : 0;         // ceil(250/16)
        float* outPrev   = hasFc ? (out + (size_t)(t - 1) * V_) : nullptr;

        // hW partials (32 slices of K=32) + fc(t-1) group 0
        carrier<<<dim3(16 + exHW, 32), 128>>>(
            h2, H_, W1 + E_, E_ + H_, 32, 32,
            nullptr, 0, nullptr, 0, 32,
            16, H_, h2, fcW, 0, cnt);

        attn_sc<<<B_, 1024>>>(W2, b2, b1);
        attn_ctx<<<dim3(E_ / 128, B_), 512>>>(x, tseq, emb, t);

        // layer 0 gates: segA inp0@Wih0 (8x192), segB h0@Whh0 (8x128) + fc grp 1
        carrier<<<dim3(64 + exG, 16), 128>>>(
            inp0, 2 * E_, Wih[0], 2 * E_, 192, 8,
            h0, H_, Whh[0], H_, 128,
            64, 4 * H_, h2, fcW, 250, cnt);
        lstm_pw<<<B_, 1024>>>(0);

        // layer 1 + fc grp 2
        carrier<<<dim3(64 + exG, 16), 128>>>(
            h0, H_, Wih[1], H_, 128, 8,
            h1, H_, Whh[1], H_, 128,
            64, 4 * H_, h2, fcW, 500, cnt);
        lstm_pw<<<B_, 1024>>>(1);

        // layer 2 + fc grp 3
        carrier<<<dim3(64 + exG, 16), 128>>>(
            h1, H_, Wih[2], H_, 128, 8,
            h2, H_, Whh[2], H_, 128,
            64, 4 * H_, h2, fcW, 750, cnt);

        // lp2(t) fused with log_softmax(t-1)
        lp2_ls<<<2 * B_, 1024>>>(outPrev, fcb);
    }

    // final step's fc (all 1000 tiles) + log_softmax
    carrier<<<dim3(63, 16), 128>>>(
        nullptr, 0, nullptr, 0, 32, 16,
        nullptr, 0, nullptr, 0, 32,
        0, H_, h2, fcW, 0, 1000);
    ls_final<<<B_, 1024>>>(out + (size_t)(T_ - 1) * V_, fcb);
}

// round 13
// speedup vs baseline: 1.1192x; 1.1192x over previous
#include <cuda_runtime.h>
#include <math.h>
#include <stdint.h>

#define B_  32
#define S1_ 128
#define T_  50
#define E_  768
#define H_  1024
#define V_  32000

// ---------------- device scratch (no allocation allowed) ----------------
__device__ float g_xW[B_ * S1_ * H_];      // x @ W1x^T (precomputed once)
__device__ float g_inp0[B_ * 2 * E_];      // [emb_t ; context]
__device__ float g_h[3 * B_ * H_];
__device__ float g_c[3 * B_ * H_];
__device__ float g_bsum[3 * 4 * H_];       // bih + bhh per layer
__device__ float g_part[16 * B_ * 4 * H_]; // split-K partials (16 x 32 x 4096)
__device__ float g_fcpart[2 * 4 * B_ * V_];// fc partials, double-buffered sets
__device__ int   g_cnt[3 * T_];            // spin counters (per step, per layer)

// ---------------- f32x2 packed helpers ----------------
__device__ __forceinline__ unsigned long long ffma2_(unsigned long long a,
                                                     unsigned long long b,
                                                     unsigned long long c) {
    unsigned long long d;
    asm("fma.rn.f32x2 %0, %1, %2, %3;" : "=l"(d) : "l"(a), "l"(b), "l"(c));
    return d;
}
__device__ __forceinline__ unsigned long long bcast2_(float x) {
    unsigned long long r;
    asm("mov.b64 %0, {%1, %1};" : "=l"(r) : "f"(x));
    return r;
}
__device__ __forceinline__ void unpack2_(unsigned long long v, float& lo, float& hi) {
    asm("mov.b64 {%0, %1}, %2;" : "=f"(lo), "=f"(hi) : "l"(v));
}
// TF32 operand rounding (matches cublas TF32 path: cvt.rna)
__device__ __forceinline__ float tf32r(float x) {
    unsigned u;
    asm("cvt.rna.tf32.f32 %0, %1;" : "=r"(u) : "f"(x));
    return __uint_as_float(u);
}

#define SHA_STRIDE 1152   // 32*36
#define SHW_STRIDE 2112   // 32*66

// ---------------- shared GEMM core: 32 rows x 64 cols per block, 128 threads
// Ping-pong double-buffered smem: ONE __syncthreads per K-chunk.
__device__ __forceinline__ void gemm_core32(
    const float* __restrict__ A, int ldA,
    const float* __restrict__ W, int ldW,
    int kbase, int NC, int nbase,
    float* __restrict__ dst, int Nout,
    float* shA, float* shW)
{
    const int tid = threadIdx.x;
    const int ng  = tid & 31;
    const int mg  = tid >> 5;
    const int m0  = mg * 8;

    unsigned long long acc0[4], acc1[4];
#pragma unroll
    for (int r = 0; r < 4; r++) { acc0[r] = 0ull; acc1[r] = 0ull; }

    float4 aR[2], wR[4];
    auto loadChunk = [&](int c) {
        const int k0 = kbase + c * 32;
#pragma unroll
        for (int j = 0; j < 2; j++) {
            const int f4 = tid + j * 128;
            const int m  = f4 >> 3, kq = f4 & 7;
            aR[j] = *reinterpret_cast<const float4*>(&A[(size_t)m * ldA + k0 + kq * 4]);
        }
#pragma unroll
        for (int j = 0; j < 4; j++) {
            const int f4 = tid + j * 128;
            const int r  = f4 >> 3, kq = f4 & 7;
            wR[j] = *reinterpret_cast<const float4*>(
                &W[(size_t)(nbase + r) * ldW + k0 + kq * 4]);
        }
    };

    loadChunk(0);
    for (int c = 0; c < NC; c++) {
        float* sA = shA + (c & 1) * SHA_STRIDE;
        float* sW = shW + (c & 1) * SHW_STRIDE;
#pragma unroll
        for (int j = 0; j < 2; j++) {
            const int f4 = tid + j * 128;
            const int m  = f4 >> 3, kq = f4 & 7;
            sA[(kq * 4 + 0) * 36 + m] = tf32r(aR[j].x);
            sA[(kq * 4 + 1) * 36 + m] = tf32r(aR[j].y);
            sA[(kq * 4 + 2) * 36 + m] = tf32r(aR[j].z);
            sA[(kq * 4 + 3) * 36 + m] = tf32r(aR[j].w);
        }
#pragma unroll
        for (int j = 0; j < 4; j++) {
            const int f4 = tid + j * 128;
            const int r  = f4 >> 3, kq = f4 & 7;
            sW[(kq * 4 + 0) * 66 + r] = tf32r(wR[j].x);
            sW[(kq * 4 + 1) * 66 + r] = tf32r(wR[j].y);
            sW[(kq * 4 + 2) * 66 + r] = tf32r(wR[j].z);
            sW[(kq * 4 + 3) * 66 + r] = tf32r(wR[j].w);
        }
        __syncthreads();
        if (c + 1 < NC) loadChunk(c + 1);

#pragma unroll
        for (int kk = 0; kk < 32; kk++) {
            const ulonglong2 a01 = *reinterpret_cast<const ulonglong2*>(&sA[kk * 36 + m0]);
            const ulonglong2 a23 = *reinterpret_cast<const ulonglong2*>(&sA[kk * 36 + m0 + 4]);
            const float2 wv = *reinterpret_cast<const float2*>(&sW[kk * 66 + 2 * ng]);
            const unsigned long long w0 = bcast2_(wv.x);
            const unsigned long long w1 = bcast2_(wv.y);
            acc0[0] = ffma2_(a01.x, w0, acc0[0]);
            acc0[1] = ffma2_(a01.y, w0, acc0[1]);
            acc0[2] = ffma2_(a23.x, w0, acc0[2]);
            acc0[3] = ffma2_(a23.y, w0, acc0[3]);
            acc1[0] = ffma2_(a01.x, w1, acc1[0]);
            acc1[1] = ffma2_(a01.y, w1, acc1[1]);
            acc1[2] = ffma2_(a23.x, w1, acc1[2]);
            acc1[3] = ffma2_(a23.y, w1, acc1[3]);
        }
    }

    const int n0 = nbase + 2 * ng;
#pragma unroll
    for (int r = 0; r < 4; r++) {
        float lo, hi;
        const int m = m0 + 2 * r;
        unpack2_(acc0[r], lo, hi);
        dst[(size_t)m * Nout + n0]           = lo;
        dst[(size_t)(m + 1) * Nout + n0]     = hi;
        unpack2_(acc1[r], lo, hi);
        dst[(size_t)m * Nout + n0 + 1]       = lo;
        dst[(size_t)(m + 1) * Nout + n0 + 1] = hi;
    }
}

// ---------------- LSTM pointwise: one (b, 128-j chunk), 128 threads ----------
__device__ __forceinline__ void lstm_update_chunk(int l, int b, int j0)
{
    const int j = j0 + threadIdx.x;
    float gi = g_bsum[l * 4 * H_ + j];
    float gf = g_bsum[l * 4 * H_ + H_ + j];
    float gg = g_bsum[l * 4 * H_ + 2 * H_ + j];
    float go = g_bsum[l * 4 * H_ + 3 * H_ + j];
#pragma unroll
    for (int ks = 0; ks < 16; ks++) {
        const float* p = g_part + (size_t)(ks * 32 + b) * 4 * H_;
        gi += p[j];
        gf += p[H_ + j];
        gg += p[2 * H_ + j];
        go += p[3 * H_ + j];
    }
    float* cp = g_c + (size_t)(l * B_ + b) * H_ + j;
    float* hp = g_h + (size_t)(l * B_ + b) * H_ + j;
    const float si = 1.f / (1.f + expf(-gi));
    const float sf = 1.f / (1.f + expf(-gf));
    const float so = 1.f / (1.f + expf(-go));
    const float cn = sf * (*cp) + si * tanhf(gg);
    *cp = cn;
    *hp = so * tanhf(cn);
}

// ---------------- log_softmax row, 128 threads, reads 4 fc partial slices ----
__device__ __forceinline__ void ls_row128(float* __restrict__ rowBase,
                                          const float* __restrict__ fcb,
                                          int b, int set, float* red)
{
    float* row = rowBase + (size_t)b * ((long long)T_ * V_);
    const int tid = threadIdx.x;
    const int NV4 = V_ / 4;
    const float* fb = g_fcpart + (size_t)set * 4 * B_ * V_;
    const float4* bb = (const float4*)fcb;
    const float4* p0 = (const float4*)(fb + (size_t)b * V_);
    const float4* p1 = (const float4*)(fb + (size_t)(B_ + b) * V_);
    const float4* p2 = (const float4*)(fb + (size_t)(2 * B_ + b) * V_);
    const float4* p3 = (const float4*)(fb + (size_t)(3 * B_ + b) * V_);
    float4* r4 = (float4*)row;

    float m = -1e30f;
    for (int v = tid; v < NV4; v += 128) {
        const float4 a = bb[v], q0 = p0[v], q1 = p1[v], q2 = p2[v], q3 = p3[v];
        float4 r;
        r.x = a.x + q0.x + q1.x + q2.x + q3.x;
        r.y = a.y + q0.y + q1.y + q2.y + q3.y;
        r.z = a.z + q0.z + q1.z + q2.z + q3.z;
        r.w = a.w + q0.w + q1.w + q2.w + q3.w;
        r4[v] = r;
        m = fmaxf(m, fmaxf(fmaxf(r.x, r.y), fmaxf(r.z, r.w)));
    }
    red[tid] = m; __syncthreads();
    for (int st = 64; st > 0; st >>= 1) {
        if (tid < st) red[tid] = fmaxf(red[tid], red[tid + st]);
        __syncthreads();
    }
    m = red[0];
    __syncthreads();

    float s = 0.f;
    for (int v = tid; v < NV4; v += 128) {
        const float4 r = r4[v];
        s += expf(r.x - m) + expf(r.y - m) + expf(r.z - m) + expf(r.w - m);
    }
    red[tid] = s; __syncthreads();
    for (int st = 64; st > 0; st >>= 1) {
        if (tid < st) red[tid] += red[tid + st];
        __syncthreads();
    }
    const float lse = logf(red[0]);

    for (int v = tid; v < NV4; v += 128) {
        float4 r = r4[v];
        r.x = (r.x - m) - lse;
        r.y = (r.y - m) - lse;
        r.z = (r.z - m) - lse;
        r.w = (r.w - m) - lse;
        r4[v] = r;
    }
}

// ---------------- carrier: main split-K GEMM + fc piggyback + aux blocks -----
// x-block layout: [0, mainBx) main | [mainBx, mainBx+fcXB) fc | rest aux.
// auxMode: 0 none, 1 = spin-fused lstm_pw(auxLayer), 2 = ls(prev output).
__global__ void __launch_bounds__(128) carrier(
    const float* __restrict__ Ain, int ldAa, const float* __restrict__ WA, int ldWA,
    int KsA, int yA,
    const float* __restrict__ Bin, int ldBb, const float* __restrict__ WB, int ldWB,
    int KsB,
    int mainBx, int N,
    const float* __restrict__ fcA, const float* __restrict__ fcW,
    int fcBase, int fcCount, int fcXB, int fcSet,
    int auxMode, int auxLayer, int* cnt, int cntTarget, int fcInc,
    float* lsOut, const float* __restrict__ fcb, int lsSet)
{
    __shared__ __align__(16) float shA[2 * SHA_STRIDE];
    __shared__ __align__(16) float shW[2 * SHW_STRIDE];
    __shared__ float red[128];
    const int bx = blockIdx.x, by = blockIdx.y;

    if (bx < mainBx) {
        const float* A; int ldA; const float* W; int ldW; int Ks, kb;
        if (by < yA) { A = Ain; ldA = ldAa; W = WA; ldW = ldWA; Ks = KsA; kb = by * KsA; }
        else         { A = Bin; ldA = ldBb; W = WB; ldW = ldWB; Ks = KsB; kb = (by - yA) * KsB; }
        gemm_core32(A, ldA, W, ldW, kb, Ks >> 5, bx * 64,
                    g_part + (size_t)by * 32 * N, N, shA, shW);
        if (cnt) {
            __threadfence();
            __syncthreads();
            if (threadIdx.x == 0) atomicAdd(cnt, 1);
        }
    } else if (bx < mainBx + fcXB) {
        const int local = (bx - mainBx) * gridDim.y + by;
        if (local < fcCount) {
            const int flat  = fcBase + local;
            const int slice = flat / 500;
            const int tile  = flat - slice * 500;
            gemm_core32(fcA, H_, fcW, H_, slice * 256, 8, tile * 64,
                        g_fcpart + (size_t)fcSet * 4 * B_ * V_ + (size_t)slice * B_ * V_,
                        V_, shA, shW);
            if (fcInc && cnt) {
                __threadfence();
                __syncthreads();
                if (threadIdx.x == 0) atomicAdd(cnt, 1);
            }
        }
    } else {
        const int local = (bx - mainBx - fcXB) * gridDim.y + by;
        if (auxMode == 1) {
            if (local < 256) {
                // spin until all producers have committed their partials
                if (threadIdx.x == 0) {
                    while (atomicAdd(cnt, 0) < cntTarget) __nanosleep(128);
                }
                __syncthreads();
                __threadfence();   // acquire
                lstm_update_chunk(auxLayer, local >> 3, (local & 7) * 128);
            }
        } else if (auxMode == 2) {
            if (local < 32) ls_row128(lsOut, fcb, local, lsSet, red);
        }
    }
}

// ---------------- xW precompute: g_xW = x @ W1x^T (4096 rows via blockIdx.z)
__global__ void __launch_bounds__(128) gemm_xw(const float* __restrict__ x,
                                               const float* __restrict__ W1)
{
    __shared__ __align__(16) float shA[2 * SHA_STRIDE];
    __shared__ __align__(16) float shW[2 * SHW_STRIDE];
    const int z = blockIdx.z;
    gemm_core32(x + (size_t)z * 32 * E_, E_, W1, E_ + H_, 0, E_ / 32, blockIdx.x * 64,
                g_xW + (size_t)z * 32 * H_, H_, shA, shW);
}

// ---------------- fused attention: hW reduce(+b1) -> scores -> logw -> context
__global__ void __launch_bounds__(1024) attn_all(
    const float* __restrict__ x, const int* __restrict__ tseq,
    const float* __restrict__ emb, const float* __restrict__ w2,
    const float* __restrict__ b2p, const float* __restrict__ b1, int t)
{
    const int b = blockIdx.x, tid = threadIdx.x;
    __shared__ float hw[H_];
    __shared__ float w2s[H_];
    __shared__ float sc[S1_];
    __shared__ float red4[4];

    {   // hW = b1 + sum of 16 partials (N=1024 layout in g_part)
        float v = b1[tid];
#pragma unroll
        for (int ks = 0; ks < 16; ks++)
            v += g_part[(size_t)(ks * 32 + b) * H_ + tid];
        hw[tid]  = v;
        w2s[tid] = w2[tid];
    }
    __syncthreads();

    const int lane = tid & 31, w = tid >> 5;
#pragma unroll
    for (int r = 0; r < 4; r++) {
        const int s = r * 32 + w;
        const float* xw = g_xW + ((size_t)b * S1_ + s) * H_;
        float p = 0.f;
#pragma unroll 8
        for (int i = 0; i < 32; i++) {
            const int hh = i * 32 + lane;
            float v = xw[hh] + hw[hh];
            v = fmaxf(v, 0.f);
            p += v * w2s[hh];
        }
#pragma unroll
        for (int o = 16; o > 0; o >>= 1) p += __shfl_xor_sync(0xffffffffu, p, o);
        if (lane == 0) sc[s] = p + b2p[0];
    }
    __syncthreads();

    if (tid < 128) {
        float v = sc[tid];
#pragma unroll
        for (int o = 16; o > 0; o >>= 1) v = fmaxf(v, __shfl_xor_sync(0xffffffffu, v, o));
        if (lane == 0) red4[w] = v;
    }
    __syncthreads();
    const float mx = fmaxf(fmaxf(red4[0], red4[1]), fmaxf(red4[2], red4[3]));
    __syncthreads();
    if (tid < 128) {
        const float sh = sc[tid] - mx;
        sc[tid] = sh;
        float e = expf(sh);
#pragma unroll
        for (int o = 16; o > 0; o >>= 1) e += __shfl_xor_sync(0xffffffffu, e, o);
        if (lane == 0) red4[w] = e;
    }
    __syncthreads();
    const float lse = logf(red4[0] + red4[1] + red4[2] + red4[3]);
    __syncthreads();
    if (tid < 128) sc[tid] -= lse;       // logw
    __syncthreads();

    if (tid < E_) {
        const float* xb = x + (size_t)b * S1_ * E_ + tid;
        float ctx = 0.f;
#pragma unroll 8
        for (int s = 0; s < S1_; s++) ctx += sc[s] * xb[(size_t)s * E_];
        g_inp0[b * 2 * E_ + E_ + tid] = ctx;
        const int tgt = tseq[b * T_ + t];
        g_inp0[b * 2 * E_ + tid] = emb[(size_t)tgt * E_ + tid];
    }
}

// ---------------- standalone ls (tail) ----------------
__global__ void __launch_bounds__(128) ls_tail(float* outBase, const float* __restrict__ fcb,
                                               int set)
{
    __shared__ float red[128];
    ls_row128(outBase, fcb, blockIdx.x, set, red);
}

// ---------------- init ----------------
__global__ void zero_state()
{
    const int idx = blockIdx.x * 1024 + threadIdx.x;
    if (idx < 3 * B_ * H_) { g_h[idx] = 0.f; g_c[idx] = 0.f; }
    if (idx < 3 * T_) g_cnt[idx] = 0;
}
__global__ void bias_sum(const float* bi0, const float* bh0,
                         const float* bi1, const float* bh1,
                         const float* bi2, const float* bh2)
{
    const int i = blockIdx.x * 1024 + threadIdx.x;
    if (i < 4 * H_) {
        g_bsum[i]          = bi0[i] + bh0[i];
        g_bsum[4 * H_ + i] = bi1[i] + bh1[i];
        g_bsum[8 * H_ + i] = bi2[i] + bh2[i];
    }
}

// ---------------- launch ----------------
extern "C" void kernel_launch(void* const* d_in, const int* in_sizes, int n_in,
                              void* d_out, int out_size)
{
    const float* x    = (const float*)d_in[0];
    const int*   tseq = (const int*)  d_in[1];
    const float* emb  = (const float*)d_in[2];
    const float* W1   = (const float*)d_in[3];   // (H, E+H)
    const float* b1   = (const float*)d_in[4];
    const float* W2   = (const float*)d_in[5];   // (1, H)
    const float* b2   = (const float*)d_in[6];

    const float *fcW, *fcb;
    const float *Wih[3], *Whh[3], *bih[3], *bhh[3];
    int base;
    if (in_sizes[7] == V_ * H_) {          // dict order (expected)
        fcW = (const float*)d_in[7];
        fcb = (const float*)d_in[8];
        base = 9;
    } else {                                // signature order (fallback)
        fcW = (const float*)d_in[19];
        fcb = (const float*)d_in[20];
        base = 7;
    }
    for (int l = 0; l < 3; l++) {
        Wih[l] = (const float*)d_in[base + 4 * l + 0];
        Whh[l] = (const float*)d_in[base + 4 * l + 1];
        bih[l] = (const float*)d_in[base + 4 * l + 2];
        bhh[l] = (const float*)d_in[base + 4 * l + 3];
    }
    float* out = (float*)d_out;

    float *inp0, *h;
    int* cntBase;
    cudaGetSymbolAddress((void**)&inp0,    g_inp0);
    cudaGetSymbolAddress((void**)&h,       g_h);
    cudaGetSymbolAddress((void**)&cntBase, g_cnt);
    float* h0 = h;
    float* h1 = h + B_ * H_;
    float* h2 = h + 2 * B_ * H_;

    zero_state<<<96, 1024>>>();
    bias_sum<<<4, 1024>>>(bih[0], bhh[0], bih[1], bhh[1], bih[2], bhh[2]);
    gemm_xw<<<dim3(16, 1, (B_ * S1_) / 32), 128>>>(x, W1);

    for (int t = 0; t < T_; t++) {
        const bool hasFc = (t > 0);          // fc of output t-1
        const bool hasLs = (t >= 2);         // log_softmax of output t-2
        const int  cnt   = hasFc ? 500 : 0;
        const int  exFc  = hasFc ? 32 : 0;   // fc x-blocks (32*16=512 slots)
        const int  fcSet = (t - 1) & 1;
        const int  lsSet = (t - 2) & 1;
        float* lsOut = hasLs ? (out + (size_t)(t - 2) * V_) : nullptr;

        // [hW (16x16, K=64 slices) | fc grp 0 | ls(t-2)]
        carrier<<<dim3(16 + exFc + (hasLs ? 2 : 0), 16), 128>>>(
            h2, H_, W1 + E_, E_ + H_, 64, 16,
            nullptr, 0, nullptr, 0, 32,
            16, H_,
            h2, fcW, 0, cnt, exFc, fcSet,
            hasLs ? 2 : 0, 0, nullptr, 0, 0,
            lsOut, fcb, lsSet);

        attn_all<<<B_, 1024>>>(x, tseq, emb, W2, b2, b1, t);

        // [g0: inp0@Wih0 (8x192) + h0@Whh0 (8x128) | fc grp 1 | lp0 spin]
        carrier<<<dim3(64 + exFc + 16, 16), 128>>>(
            inp0, 2 * E_, Wih[0], 2 * E_, 192, 8,
            h0, H_, Whh[0], H_, 128,
            64, 4 * H_,
            h2, fcW, 500, cnt, exFc, fcSet,
            1, 0, cntBase + t * 3 + 0, 1024, 0,
            nullptr, nullptr, 0);

        // [g1 | fc grp 2 | lp1 spin]
        carrier<<<dim3(64 + exFc + 16, 16), 128>>>(
            h0, H_, Wih[1], H_, 128, 8,
            h1, H_, Whh[1], H_, 128,
            64, 4 * H_,
            h2, fcW, 1000, cnt, exFc, fcSet,
            1, 1, cntBase + t * 3 + 1, 1024, 0,
            nullptr, nullptr, 0);

        // [g2 | fc grp 3 (reads h2 -> counted) | lp2 spin]
        carrier<<<dim3(64 + exFc + 16, 16), 128>>>(
            h1, H_, Wih[2], H_, 128, 8,
            h2, H_, Whh[2], H_, 128,
            64, 4 * H_,
            h2, fcW, 1500, cnt, exFc, fcSet,
            1, 2, cntBase + t * 3 + 2, 1024 + cnt, 1,
            nullptr, nullptr, 0);
    }

    // tail: ls(T-2), then fc(T-1) full, then ls(T-1)
    ls_tail<<<B_, 128>>>(out + (size_t)(T_ - 2) * V_, fcb, (T_ - 2) & 1);
    carrier<<<dim3(125, 16), 128>>>(
        nullptr, 0, nullptr, 0, 32, 16,
        nullptr, 0, nullptr, 0, 32,
        0, H_,
        h2, fcW, 0, 2000, 125, (T_ - 1) & 1,
        0, 0, nullptr, 0, 0,
        nullptr, nullptr, 0);
    ls_tail<<<B_, 128>>>(out + (size_t)(T_ - 1) * V_, fcb, (T_ - 1) & 1);
}